// round 1
// baseline (speedup 1.0000x reference)
#include <cuda_runtime.h>
#include <cuda_bf16.h>
#include <cstdint>

// Problem constants
#define BATCH 16
#define HGRID 64
#define WGRID 64
#define DIM   512
#define NTOK  (1 + HGRID * WGRID)     // 4097

// Tiling
#define CT        32                  // channels per block (16 float2 lanes)
#define LANES     16
#define TILE      16                  // 16x16 spatial tile per block
#define TIN       22                  // TILE + 6 halo
#define SPOS      (TIN * TIN)         // 484
#define NW        49                  // 7x7 fused taps
#define THREADS   128                 // 16 lanes x 8 spatial workers

#define SMEM_ULL  (SPOS * LANES + NW * LANES)     // 7744 + 784 = 8528
#define SMEM_BYTES (SMEM_ULL * 8)                 // 68224

// Fused weights / bias scratch (allocation-free: device globals)
__device__ __align__(16) float g_wf[NW * DIM];    // layout [k][c]
__device__ __align__(16) float g_bsum[DIM];

__device__ __forceinline__ unsigned long long fma2(unsigned long long a,
                                                   unsigned long long b,
                                                   unsigned long long c) {
    unsigned long long d;
    asm("fma.rn.f32x2 %0, %1, %2, %3;" : "=l"(d) : "l"(a), "l"(b), "l"(c));
    return d;
}

// ---------------------------------------------------------------------------
// Prep: fuse w7 + pad(w5) + pad(w3) + identity into one 7x7 kernel, sum biases
// ---------------------------------------------------------------------------
__global__ void prep_kernel(const float* __restrict__ w7, const float* __restrict__ b7,
                            const float* __restrict__ w5, const float* __restrict__ b5,
                            const float* __restrict__ w3, const float* __restrict__ b3) {
    int idx = blockIdx.x * blockDim.x + threadIdx.x;
    if (idx < NW * DIM) {
        int k = idx / DIM;
        int c = idx - k * DIM;
        int kr = k / 7, kc = k - kr * 7;
        float v = w7[c * 49 + k];
        if (kr >= 1 && kr <= 5 && kc >= 1 && kc <= 5)
            v += w5[c * 25 + (kr - 1) * 5 + (kc - 1)];
        if (kr >= 2 && kr <= 4 && kc >= 2 && kc <= 4)
            v += w3[c * 9 + (kr - 2) * 3 + (kc - 2)];
        if (kr == 3 && kc == 3) v += 1.0f;
        g_wf[idx] = v;
    }
    if (idx < DIM) g_bsum[idx] = b7[idx] + b5[idx] + b3[idx];
}

// ---------------------------------------------------------------------------
// cls token pass-through
// ---------------------------------------------------------------------------
__global__ void cls_copy_kernel(const float* __restrict__ x, float* __restrict__ out) {
    int idx = blockIdx.x * blockDim.x + threadIdx.x;   // 16*512
    int b = idx >> 9;
    int c = idx & 511;
    size_t off = (size_t)b * NTOK * DIM + c;
    out[off] = x[off];
}

// ---------------------------------------------------------------------------
// Fused 7x7 depthwise conv (float2 packed, FFMA2)
// grid: (C/CT=16, 16 spatial tiles, B=16), block: (16, 8)
// ---------------------------------------------------------------------------
__global__ void __launch_bounds__(THREADS, 3)
conv_kernel(const float* __restrict__ x, float* __restrict__ out) {
    extern __shared__ unsigned long long sm[];
    unsigned long long* s_in = sm;                 // [SPOS][LANES]
    unsigned long long* s_w  = sm + SPOS * LANES;  // [NW][LANES]

    const int tid  = threadIdx.y * LANES + threadIdx.x;
    const int lane = tid & (LANES - 1);
    const int pg   = tid >> 4;                     // 0..7

    const int c0 = blockIdx.x * CT;
    const int h0 = (blockIdx.y >> 2) * TILE;
    const int w0 = (blockIdx.y & 3) * TILE;
    const int b  = blockIdx.z;

    const unsigned long long* x64 = (const unsigned long long*)x;
    unsigned long long* o64       = (unsigned long long*)out;
    const int  cl      = (c0 >> 1) + lane;         // ull index in channel dim
    const long tokbase = (long)b * NTOK + 1;       // skip cls token

    // Stage input tile (22x22 x 32ch) with zero-padded halo
    #pragma unroll 4
    for (int p = pg; p < SPOS; p += 8) {
        int row = p / TIN;
        int col = p - row * TIN;
        int gh = h0 + row - 3;
        int gw = w0 + col - 3;
        unsigned long long v = 0ull;
        if ((unsigned)gh < (unsigned)HGRID && (unsigned)gw < (unsigned)WGRID)
            v = x64[(tokbase + gh * WGRID + gw) * (DIM / 2) + cl];
        s_in[p * LANES + lane] = v;
    }
    // Stage fused weights for this channel group
    for (int i = tid; i < NW * LANES; i += THREADS) {
        int k = i >> 4;
        s_w[i] = *(const unsigned long long*)&g_wf[k * DIM + c0 + 2 * lane];
    }
    const unsigned long long bv =
        *(const unsigned long long*)&g_bsum[c0 + 2 * lane];

    __syncthreads();

    // Per-thread output patch: 4 rows x 8 cols
    const int r0 = (threadIdx.y >> 1) * 4;   // 0,4,8,12
    const int q0 = (threadIdx.y & 1) * 8;    // 0 or 8

    unsigned long long acc[4][8];
    #pragma unroll
    for (int r = 0; r < 4; ++r)
        #pragma unroll
        for (int c = 0; c < 8; ++c)
            acc[r][c] = bv;

    #pragma unroll
    for (int ir = 0; ir < 10; ++ir) {
        const int srow = r0 + ir;            // 0..21
        unsigned long long in[14];
        #pragma unroll
        for (int j = 0; j < 14; ++j)
            in[j] = s_in[(srow * TIN + q0 + j) * LANES + lane];

        #pragma unroll
        for (int kr = 0; kr < 7; ++kr) {
            const int r = ir - kr;           // compile-time after unroll
            if (r < 0 || r > 3) continue;
            #pragma unroll
            for (int kc = 0; kc < 7; ++kc) {
                const unsigned long long w = s_w[(kr * 7 + kc) * LANES + lane];
                #pragma unroll
                for (int c = 0; c < 8; ++c)
                    acc[r][c] = fma2(in[c + kc], w, acc[r][c]);
            }
        }
    }

    // Store results
    #pragma unroll
    for (int r = 0; r < 4; ++r) {
        const long rowtok = tokbase + (long)(h0 + r0 + r) * WGRID + (w0 + q0);
        #pragma unroll
        for (int c = 0; c < 8; ++c)
            o64[(rowtok + c) * (DIM / 2) + cl] = acc[r][c];
    }
}

// ---------------------------------------------------------------------------
extern "C" void kernel_launch(void* const* d_in, const int* in_sizes, int n_in,
                              void* d_out, int out_size) {
    const float* x  = (const float*)d_in[0];
    const float* w7 = (const float*)d_in[1];
    const float* b7 = (const float*)d_in[2];
    const float* w5 = (const float*)d_in[3];
    const float* b5 = (const float*)d_in[4];
    const float* w3 = (const float*)d_in[5];
    const float* b3 = (const float*)d_in[6];
    float* out = (float*)d_out;

    cudaFuncSetAttribute(conv_kernel,
                         cudaFuncAttributeMaxDynamicSharedMemorySize, SMEM_BYTES);

    prep_kernel<<<(NW * DIM + 255) / 256, 256>>>(w7, b7, w5, b5, w3, b3);
    cls_copy_kernel<<<(BATCH * DIM) / 256, 256>>>(x, out);

    dim3 grid(DIM / CT, (HGRID / TILE) * (WGRID / TILE), BATCH);  // 16,16,16
    dim3 blk(LANES, 8);
    conv_kernel<<<grid, blk, SMEM_BYTES>>>(x, out);
}

// round 2
// speedup vs baseline: 1.0117x; 1.0117x over previous
#include <cuda_runtime.h>
#include <cuda_bf16.h>
#include <cstdint>

// Problem constants
#define BATCH 16
#define HGRID 64
#define WGRID 64
#define DIM   512
#define NTOK  (1 + HGRID * WGRID)     // 4097

// Tiling
#define CT        32                  // channels per block (16 float2 lanes)
#define LANES     16
#define TILE      16                  // 16x16 spatial tile per block
#define TIN       22                  // TILE + 6 halo
#define SPOS      (TIN * TIN)         // 484
#define PS        17                  // padded lane-stride (ull) -> conflict-free
#define NW        49                  // 7x7 fused taps
#define THREADS   128                 // 16 lanes x 8 spatial workers

#define SMEM_ULL  (SPOS * PS + NW * LANES)        // 8228 + 784 = 9012
#define SMEM_BYTES (SMEM_ULL * 8)                 // 72096

// Fused weights / bias scratch (allocation-free: device globals)
__device__ __align__(16) float g_wf[NW * DIM];    // layout [k][c]
__device__ __align__(16) float g_bsum[DIM];

__device__ __forceinline__ unsigned long long fma2(unsigned long long a,
                                                   unsigned long long b,
                                                   unsigned long long c) {
    unsigned long long d;
    asm("fma.rn.f32x2 %0, %1, %2, %3;" : "=l"(d) : "l"(a), "l"(b), "l"(c));
    return d;
}

// ---------------------------------------------------------------------------
// Prep: fuse w7 + pad(w5) + pad(w3) + identity into one 7x7 kernel, sum biases
// ---------------------------------------------------------------------------
__global__ void prep_kernel(const float* __restrict__ w7, const float* __restrict__ b7,
                            const float* __restrict__ w5, const float* __restrict__ b5,
                            const float* __restrict__ w3, const float* __restrict__ b3) {
    int idx = blockIdx.x * blockDim.x + threadIdx.x;
    if (idx < NW * DIM) {
        int k = idx / DIM;
        int c = idx - k * DIM;
        int kr = k / 7, kc = k - kr * 7;
        float v = w7[c * 49 + k];
        if (kr >= 1 && kr <= 5 && kc >= 1 && kc <= 5)
            v += w5[c * 25 + (kr - 1) * 5 + (kc - 1)];
        if (kr >= 2 && kr <= 4 && kc >= 2 && kc <= 4)
            v += w3[c * 9 + (kr - 2) * 3 + (kc - 2)];
        if (kr == 3 && kc == 3) v += 1.0f;
        g_wf[idx] = v;
    }
    if (idx < DIM) g_bsum[idx] = b7[idx] + b5[idx] + b3[idx];
}

// ---------------------------------------------------------------------------
// cls token pass-through
// ---------------------------------------------------------------------------
__global__ void cls_copy_kernel(const float* __restrict__ x, float* __restrict__ out) {
    int idx = blockIdx.x * blockDim.x + threadIdx.x;   // 16*512
    int b = idx >> 9;
    int c = idx & 511;
    size_t off = (size_t)b * NTOK * DIM + c;
    out[off] = x[off];
}

// ---------------------------------------------------------------------------
// Fused 7x7 depthwise conv (float2 packed, FFMA2)
// grid: (C/CT=16, 16 spatial tiles, B=16), block: (16, 8)
// Each thread: 4 output rows x 8 cols, processed as 2 row-pairs with
// statically-indexed accumulators (spill-proof) and padded smem (bank-safe).
// ---------------------------------------------------------------------------
__global__ void __launch_bounds__(THREADS, 3)
conv_kernel(const float* __restrict__ x, float* __restrict__ out) {
    extern __shared__ unsigned long long sm[];
    unsigned long long* s_in = sm;                 // [SPOS] stride PS
    unsigned long long* s_w  = sm + SPOS * PS;     // [NW][LANES]

    const int tid  = threadIdx.y * LANES + threadIdx.x;
    const int lane = tid & (LANES - 1);
    const int pg   = tid >> 4;                     // 0..7

    const int c0 = blockIdx.x * CT;
    const int h0 = (blockIdx.y >> 2) * TILE;
    const int w0 = (blockIdx.y & 3) * TILE;
    const int b  = blockIdx.z;

    const unsigned long long* x64 = (const unsigned long long*)x;
    unsigned long long* o64       = (unsigned long long*)out;
    const int  cl      = (c0 >> 1) + lane;         // ull index in channel dim
    const long tokbase = (long)b * NTOK + 1;       // skip cls token

    // Stage input tile (22x22 x 32ch) with zero-padded halo
    #pragma unroll 4
    for (int p = pg; p < SPOS; p += 8) {
        int row = p / TIN;
        int col = p - row * TIN;
        int gh = h0 + row - 3;
        int gw = w0 + col - 3;
        unsigned long long v = 0ull;
        if ((unsigned)gh < (unsigned)HGRID && (unsigned)gw < (unsigned)WGRID)
            v = x64[(tokbase + gh * WGRID + gw) * (DIM / 2) + cl];
        s_in[p * PS + lane] = v;
    }
    // Stage fused weights for this channel group
    for (int i = tid; i < NW * LANES; i += THREADS) {
        int k = i >> 4;
        s_w[i] = *(const unsigned long long*)&g_wf[k * DIM + c0 + 2 * lane];
    }
    const unsigned long long bv =
        *(const unsigned long long*)&g_bsum[c0 + 2 * lane];

    __syncthreads();

    // Per-thread output patch: 4 rows x 8 cols = 2 row-pairs
    const int r0 = (threadIdx.y >> 1) * 4;   // 0,4,8,12
    const int q0 = (threadIdx.y & 1) * 8;    // 0 or 8

    #pragma unroll
    for (int rp = 0; rp < 2; ++rp) {
        const int or0 = r0 + 2 * rp;         // first output row of pair

        unsigned long long a0[8], a1[8];
        #pragma unroll
        for (int c = 0; c < 8; ++c) { a0[c] = bv; a1[c] = bv; }

        #pragma unroll
        for (int ir = 0; ir < 8; ++ir) {     // input rows or0 .. or0+7
            const int srow = or0 + ir;       // 0..21
            unsigned long long in[14];
            #pragma unroll
            for (int j = 0; j < 14; ++j)
                in[j] = s_in[(srow * TIN + q0 + j) * PS + lane];

            if (ir <= 6) {                   // contributes to row0 with kr=ir
                #pragma unroll
                for (int kc = 0; kc < 7; ++kc) {
                    const unsigned long long w = s_w[(ir * 7 + kc) * LANES + lane];
                    #pragma unroll
                    for (int c = 0; c < 8; ++c)
                        a0[c] = fma2(in[c + kc], w, a0[c]);
                }
            }
            if (ir >= 1) {                   // contributes to row1 with kr=ir-1
                #pragma unroll
                for (int kc = 0; kc < 7; ++kc) {
                    const unsigned long long w = s_w[((ir - 1) * 7 + kc) * LANES + lane];
                    #pragma unroll
                    for (int c = 0; c < 8; ++c)
                        a1[c] = fma2(in[c + kc], w, a1[c]);
                }
            }
        }

        const long row0tok = tokbase + (long)(h0 + or0) * WGRID + (w0 + q0);
        const long row1tok = row0tok + WGRID;
        #pragma unroll
        for (int c = 0; c < 8; ++c) {
            o64[(row0tok + c) * (DIM / 2) + cl] = a0[c];
            o64[(row1tok + c) * (DIM / 2) + cl] = a1[c];
        }
    }
}

// ---------------------------------------------------------------------------
extern "C" void kernel_launch(void* const* d_in, const int* in_sizes, int n_in,
                              void* d_out, int out_size) {
    const float* x  = (const float*)d_in[0];
    const float* w7 = (const float*)d_in[1];
    const float* b7 = (const float*)d_in[2];
    const float* w5 = (const float*)d_in[3];
    const float* b5 = (const float*)d_in[4];
    const float* w3 = (const float*)d_in[5];
    const float* b3 = (const float*)d_in[6];
    float* out = (float*)d_out;

    cudaFuncSetAttribute(conv_kernel,
                         cudaFuncAttributeMaxDynamicSharedMemorySize, SMEM_BYTES);

    prep_kernel<<<(NW * DIM + 255) / 256, 256>>>(w7, b7, w5, b5, w3, b3);
    cls_copy_kernel<<<(BATCH * DIM) / 256, 256>>>(x, out);

    dim3 grid(DIM / CT, (HGRID / TILE) * (WGRID / TILE), BATCH);  // 16,16,16
    dim3 blk(LANES, 8);
    conv_kernel<<<grid, blk, SMEM_BYTES>>>(x, out);
}